// round 4
// baseline (speedup 1.0000x reference)
#include <cuda_runtime.h>

#define NN 20000      // nodes
#define EE 320000     // edges
#define FD 64         // features
#define HH 4          // heads
#define CC 64         // channels/head
#define HC 256        // HH*CC
#define RR 512        // relations
#define NEG 0.2f

// ---------------- scratch (device globals; no allocation anywhere) ----------------
__device__ float g_xl[NN * HC];
__device__ float g_xr[NN * HC];
__device__ float g_le[NN * HC];     // self-loop edge projection
__device__ float g_rp[RR * HC];     // relation projection table
__device__ float g_mean[NN * FD];   // per-node mean incoming edge_attr
__device__ float g_h[NN * FD];      // layer-0 output
__device__ int   g_deg[NN];
__device__ int   g_off[NN + 1];
__device__ int   g_cur[NN];
__device__ int   g_csr[EE];

// ---------------- setup kernels ----------------
__global__ void k_zero_deg() {
    int i = blockIdx.x * blockDim.x + threadIdx.x;
    if (i < NN) g_deg[i] = 0;
}

__global__ void k_zero_mean() {
    int i = blockIdx.x * blockDim.x + threadIdx.x;
    if (i < NN * FD) g_mean[i] = 0.f;
}

__global__ void k_count(const int* __restrict__ dst) {
    int e = blockIdx.x * blockDim.x + threadIdx.x;
    if (e < EE) atomicAdd(&g_deg[dst[e]], 1);
}

// scatter-add relations[ri[e]] into g_mean[dst[e]]; thread per (edge, feature)
__global__ void k_scatter_mean(const int* __restrict__ dst,
                               const int* __restrict__ ri,
                               const float* __restrict__ rel) {
    long long idx = (long long)blockIdx.x * blockDim.x + threadIdx.x;
    if (idx >= (long long)EE * FD) return;
    int e = (int)(idx >> 6);
    int f = (int)(idx & 63);
    int d = __ldg(dst + e);
    int r = __ldg(ri + e);
    atomicAdd(&g_mean[d * FD + f], __ldg(rel + r * FD + f));
}

__global__ void k_div_mean() {
    int i = blockIdx.x * blockDim.x + threadIdx.x;
    if (i >= NN * FD) return;
    int n = i >> 6;
    int d = g_deg[n];
    g_mean[i] *= 1.0f / (float)(d > 0 ? d : 1);
}

// single-block exclusive scan of g_deg -> g_off, also copies into g_cur
__global__ void k_scan() {
    __shared__ int carry;
    __shared__ int ws[32];
    int tid = threadIdx.x;
    int lane = tid & 31, wid = tid >> 5;
    if (tid == 0) carry = 0;
    __syncthreads();
    for (int base = 0; base < NN; base += 1024) {
        int idx = base + tid;
        int v = (idx < NN) ? g_deg[idx] : 0;
        int x = v;
        #pragma unroll
        for (int o = 1; o < 32; o <<= 1) {
            int y = __shfl_up_sync(0xffffffffu, x, o);
            if (lane >= o) x += y;
        }
        if (lane == 31) ws[wid] = x;
        __syncthreads();
        if (wid == 0) {
            int s = ws[lane];
            #pragma unroll
            for (int o = 1; o < 32; o <<= 1) {
                int y = __shfl_up_sync(0xffffffffu, s, o);
                if (lane >= o) s += y;
            }
            ws[lane] = s;
        }
        __syncthreads();
        int pre = carry + ((wid > 0) ? ws[wid - 1] : 0) + x - v;
        if (idx < NN) { g_off[idx] = pre; g_cur[idx] = pre; }
        __syncthreads();
        if (tid == 1023) carry = pre + v;
        __syncthreads();
    }
    if (threadIdx.x == 0) g_off[NN] = carry;
}

__global__ void k_csr(const int* __restrict__ dst) {
    int e = blockIdx.x * blockDim.x + threadIdx.x;
    if (e >= EE) return;
    int d = dst[e];
    int pos = atomicAdd(&g_cur[d], 1);
    g_csr[pos] = e;
}

// ---------------- GEMM: Y[nrows,256] = X[nrows,64] @ W[256,64]^T + bias ----------------
// X: xsel==0 -> arg pointer Xin; 1 -> g_h; 2 -> g_mean
// Y: outsel 0 -> g_xl, 1 -> g_xr, 2 -> g_le, 3 -> g_rp
__global__ void k_gemm(const float* __restrict__ Xin, int xsel,
                       const float* __restrict__ W,
                       const float* __restrict__ bias, int outsel,
                       int nrows) {
    const float* X = (xsel == 0) ? Xin : (xsel == 1) ? g_h : g_mean;
    float* Y = (outsel == 0) ? g_xl : (outsel == 1) ? g_xr : (outsel == 2) ? g_le : g_rp;

    __shared__ float Xs[32 * 64];
    int row0 = blockIdx.x * 32;
    int tid = threadIdx.x;  // 0..255, output column
    for (int i = tid; i < 32 * 64; i += 256) {
        int r = row0 + (i >> 6);
        Xs[i] = (r < nrows) ? X[(long long)row0 * 64 + i] : 0.f;
    }
    __syncthreads();
    float acc[32];
    #pragma unroll
    for (int r = 0; r < 32; r++) acc[r] = 0.f;
    const float* w = W + tid * 64;
    #pragma unroll 4
    for (int k = 0; k < 64; k++) {
        float wk = __ldg(w + k);
        #pragma unroll
        for (int r = 0; r < 32; r++) acc[r] += Xs[r * 64 + k] * wk;
    }
    float bv = bias ? bias[tid] : 0.f;
    #pragma unroll
    for (int r = 0; r < 32; r++) {
        int row = row0 + r;
        if (row < nrows) Y[(long long)row * HC + tid] = acc[r] + bv;
    }
}

// ---------------- per-node GATv2 aggregation (online softmax) ----------------
// block = 128 threads = 4 warps; warp w = head w; lane owns channels {lane, lane+32}
// grid-stride over nodes; out==nullptr means write layer-0 buffer g_h.
#define NODE_BLOCKS 1480
__global__ void __launch_bounds__(128)
k_node(const float* __restrict__ att, const float* __restrict__ bias,
       const int* __restrict__ src, const int* __restrict__ ri,
       float* __restrict__ outp) {
    float* out = outp ? outp : g_h;
    int w = threadIdx.x >> 5;        // head
    int lane = threadIdx.x & 31;
    int hb = w * CC;                 // head base in the 256-wide row

    float a0 = att[hb + lane];
    float a1 = att[hb + lane + 32];

    for (int n = blockIdx.x; n < NN; n += NODE_BLOCKS) {
        long long nb = (long long)n * HC + hb;
        float xr0 = g_xr[nb + lane];
        float xr1 = g_xr[nb + lane + 32];

        // self-loop initializes the online-softmax state
        float xl0 = g_xl[nb + lane];
        float xl1 = g_xl[nb + lane + 32];
        float e0 = g_le[nb + lane];
        float e1 = g_le[nb + lane + 32];
        float m0 = xl0 + xr0 + e0; m0 = fmaxf(m0, NEG * m0);
        float m1 = xl1 + xr1 + e1; m1 = fmaxf(m1, NEG * m1);
        float t = m0 * a0 + m1 * a1;
        #pragma unroll
        for (int o = 16; o; o >>= 1) t += __shfl_xor_sync(0xffffffffu, t, o);
        float mmax = t, denom = 1.f, acc0 = xl0, acc1 = xl1;

        int beg = g_off[n], end = g_off[n + 1];
        for (int i = beg; i < end; i++) {
            int e = __ldg(&g_csr[i]);
            int s = __ldg(src + e);
            int r = __ldg(ri + e);
            long long sb = (long long)s * HC + hb;
            long long rb = (long long)r * HC + hb;
            xl0 = g_xl[sb + lane];
            xl1 = g_xl[sb + lane + 32];
            e0 = g_rp[rb + lane];
            e1 = g_rp[rb + lane + 32];
            m0 = xl0 + xr0 + e0; m0 = fmaxf(m0, NEG * m0);
            m1 = xl1 + xr1 + e1; m1 = fmaxf(m1, NEG * m1);
            t = m0 * a0 + m1 * a1;
            #pragma unroll
            for (int o = 16; o; o >>= 1) t += __shfl_xor_sync(0xffffffffu, t, o);
            float nm = fmaxf(mmax, t);
            float sc = __expf(mmax - nm);
            float p  = __expf(t - nm);
            denom = denom * sc + p;
            acc0  = acc0 * sc + p * xl0;
            acc1  = acc1 * sc + p * xl1;
            mmax = nm;
        }

        __shared__ float sh[HH * CC];
        float inv = 1.f / denom;
        sh[hb + lane]      = acc0 * inv;
        sh[hb + lane + 32] = acc1 * inv;
        __syncthreads();
        int c = threadIdx.x;
        if (c < CC) {
            float v = 0.25f * (sh[c] + sh[CC + c] + sh[2 * CC + c] + sh[3 * CC + c]) + bias[c];
            out[(long long)n * FD + c] = v;
        }
        __syncthreads();   // protect sh before next node iteration
    }
}

__global__ void k_copyrel(const float* __restrict__ rel, float* __restrict__ out) {
    int i = blockIdx.x * blockDim.x + threadIdx.x;
    if (i < RR * FD) out[i] = rel[i];
}

// ---------------- launch: kernel launches ONLY ----------------
extern "C" void kernel_launch(void* const* d_in, const int* in_sizes, int n_in,
                              void* d_out, int out_size) {
    const float* x    = (const float*)d_in[0];
    const int*   ei   = (const int*)d_in[1];     // int32! (JAX default x64 disabled)
    const float* rel  = (const float*)d_in[2];
    const int*   ri   = (const int*)d_in[3];     // int32!
    const float* Wt[2][3] = {{(const float*)d_in[4],  (const float*)d_in[6],  (const float*)d_in[8]},
                             {(const float*)d_in[11], (const float*)d_in[13], (const float*)d_in[15]}};
    const float* Bt[2][2] = {{(const float*)d_in[5],  (const float*)d_in[7]},
                             {(const float*)d_in[12], (const float*)d_in[14]}};
    const float* At[2]    = {(const float*)d_in[9],  (const float*)d_in[16]};
    const float* bt[2]    = {(const float*)d_in[10], (const float*)d_in[17]};
    float* out = (float*)d_out;

    const int* srcA = ei;
    const int* dstA = ei + EE;

    // ---- graph setup (shared across layers) ----
    k_zero_deg<<<(NN + 255) / 256, 256>>>();
    k_zero_mean<<<(NN * FD + 255) / 256, 256>>>();
    k_count<<<(EE + 255) / 256, 256>>>(dstA);
    k_scatter_mean<<<(int)(((long long)EE * FD + 255) / 256), 256>>>(dstA, ri, rel);
    k_div_mean<<<(NN * FD + 255) / 256, 256>>>();
    k_scan<<<1, 1024>>>();
    k_csr<<<(EE + 255) / 256, 256>>>(dstA);

    // ---- two GATv2 layers ----
    for (int l = 0; l < 2; l++) {
        int xsel = l ? 1 : 0;                       // layer0: input x (arg), layer1: g_h
        float* ol = l ? out : nullptr;              // layer0 writes g_h
        k_gemm<<<(NN + 31) / 32, 256>>>(x, xsel, Wt[l][0], Bt[l][0], 0, NN);  // -> g_xl
        k_gemm<<<(NN + 31) / 32, 256>>>(x, xsel, Wt[l][1], Bt[l][1], 1, NN);  // -> g_xr
        k_gemm<<<(NN + 31) / 32, 256>>>(x, 2,    Wt[l][2], nullptr,  2, NN);  // mean -> g_le
        k_gemm<<<(RR + 31) / 32, 256>>>(rel, 0,  Wt[l][2], nullptr,  3, RR);  // rel -> g_rp
        k_node<<<NODE_BLOCKS, 128>>>(At[l], bt[l], srcA, ri, ol);
    }

    // trailing output: relations passthrough
    k_copyrel<<<(RR * FD + 255) / 256, 256>>>(rel, out + (long long)NN * FD);
}

// round 5
// speedup vs baseline: 1.6850x; 1.6850x over previous
#include <cuda_runtime.h>

#define NN 20000      // nodes
#define EE 320000     // edges
#define FD 64         // features
#define HH 4          // heads
#define CC 64         // channels/head
#define HC 256        // HH*CC
#define RR 512        // relations
#define NEG 0.2f

// ---------------- scratch (device globals; no allocation anywhere) ----------------
__device__ float g_xl[NN * HC];
__device__ float g_xr[NN * HC];
__device__ float g_le[NN * HC];     // self-loop edge projection
__device__ float g_rp[RR * HC];     // relation projection table
__device__ float g_mean[NN * FD];   // per-node mean incoming edge_attr
__device__ float g_h[NN * FD];      // layer-0 output
__device__ int   g_deg[NN];
__device__ int   g_off[NN + 1];
__device__ int   g_cur[NN];
__device__ int2  g_csrE[EE];        // packed (src, ri) per CSR slot

// ---------------- setup kernels ----------------
__global__ void k_zero_deg() {
    int i = blockIdx.x * blockDim.x + threadIdx.x;
    if (i < NN) g_deg[i] = 0;
}

__global__ void k_count(const int* __restrict__ dst) {
    int e = blockIdx.x * blockDim.x + threadIdx.x;
    if (e < EE) atomicAdd(&g_deg[dst[e]], 1);
}

// single-block exclusive scan of g_deg -> g_off, also copies into g_cur
__global__ void k_scan() {
    __shared__ int carry;
    __shared__ int ws[32];
    int tid = threadIdx.x;
    int lane = tid & 31, wid = tid >> 5;
    if (tid == 0) carry = 0;
    __syncthreads();
    for (int base = 0; base < NN; base += 1024) {
        int idx = base + tid;
        int v = (idx < NN) ? g_deg[idx] : 0;
        int x = v;
        #pragma unroll
        for (int o = 1; o < 32; o <<= 1) {
            int y = __shfl_up_sync(0xffffffffu, x, o);
            if (lane >= o) x += y;
        }
        if (lane == 31) ws[wid] = x;
        __syncthreads();
        if (wid == 0) {
            int s = ws[lane];
            #pragma unroll
            for (int o = 1; o < 32; o <<= 1) {
                int y = __shfl_up_sync(0xffffffffu, s, o);
                if (lane >= o) s += y;
            }
            ws[lane] = s;
        }
        __syncthreads();
        int pre = carry + ((wid > 0) ? ws[wid - 1] : 0) + x - v;
        if (idx < NN) { g_off[idx] = pre; g_cur[idx] = pre; }
        __syncthreads();
        if (tid == 1023) carry = pre + v;
        __syncthreads();
    }
    if (threadIdx.x == 0) g_off[NN] = carry;
}

// scatter edges into CSR with packed (src, ri) payload
__global__ void k_csr(const int* __restrict__ src, const int* __restrict__ dst,
                      const int* __restrict__ ri) {
    int e = blockIdx.x * blockDim.x + threadIdx.x;
    if (e >= EE) return;
    int d = dst[e];
    int pos = atomicAdd(&g_cur[d], 1);
    g_csrE[pos] = make_int2(src[e], ri[e]);
}

// per-node mean of incoming relation rows, via CSR gather (no atomics)
__global__ void k_mean(const float* __restrict__ rel) {
    int n = blockIdx.x;
    int f = threadIdx.x;           // 64 threads
    int beg = g_off[n], end = g_off[n + 1];
    float s = 0.f;
    for (int i = beg; i < end; i++) {
        int r = g_csrE[i].y;
        s += __ldg(rel + r * FD + f);
    }
    int d = end - beg;
    g_mean[n * FD + f] = s * (1.0f / (float)(d > 0 ? d : 1));
}

// ---------------- GEMMs: Y[rows,256] = X[rows,64] @ W[256,64]^T (+bias) ----------------
// All row counts are exact multiples of 32 (20000, 512): no bounds checks.
// Fused xl/xr GEMM: shared X tile, two weight sets.
__global__ void k_gemm2(const float* __restrict__ Xin,
                        const float* __restrict__ W0, const float* __restrict__ B0,
                        const float* __restrict__ W1, const float* __restrict__ B1,
                        int xsel) {
    const float* X = xsel ? g_h : Xin;
    __shared__ float Xs[32 * 64];
    int row0 = blockIdx.x * 32;
    int tid = threadIdx.x;  // 0..255, output column
    const float4* Xg = (const float4*)(X + (size_t)row0 * 64);
    float4* Xs4 = (float4*)Xs;
    Xs4[tid] = Xg[tid];
    Xs4[tid + 256] = Xg[tid + 256];
    __syncthreads();
    #pragma unroll 1
    for (int o = 0; o < 2; o++) {
        const float* W = o ? W1 : W0;
        const float* B = o ? B1 : B0;
        float* Y = o ? g_xr : g_xl;
        float acc[32];
        #pragma unroll
        for (int r = 0; r < 32; r++) acc[r] = 0.f;
        const float4* w4 = (const float4*)(W + tid * 64);
        #pragma unroll
        for (int k4 = 0; k4 < 16; k4++) {
            float4 wv = __ldg(&w4[k4]);
            #pragma unroll
            for (int r = 0; r < 32; r++) {
                float4 xv = *(const float4*)&Xs[r * 64 + k4 * 4];
                acc[r] += xv.x * wv.x + xv.y * wv.y + xv.z * wv.z + xv.w * wv.w;
            }
        }
        float bv = B[tid];
        #pragma unroll
        for (int r = 0; r < 32; r++)
            Y[(size_t)(row0 + r) * HC + tid] = acc[r] + bv;
    }
}

// single-output, bias-free GEMM: xsel 0 -> Xin arg, 1 -> g_mean; outsel 0 -> g_le, 1 -> g_rp
__global__ void k_gemm1(const float* __restrict__ Xin, int xsel,
                        const float* __restrict__ W, int outsel) {
    const float* X = xsel ? g_mean : Xin;
    float* Y = outsel ? g_rp : g_le;
    __shared__ float Xs[32 * 64];
    int row0 = blockIdx.x * 32;
    int tid = threadIdx.x;
    const float4* Xg = (const float4*)(X + (size_t)row0 * 64);
    float4* Xs4 = (float4*)Xs;
    Xs4[tid] = Xg[tid];
    Xs4[tid + 256] = Xg[tid + 256];
    __syncthreads();
    float acc[32];
    #pragma unroll
    for (int r = 0; r < 32; r++) acc[r] = 0.f;
    const float4* w4 = (const float4*)(W + tid * 64);
    #pragma unroll
    for (int k4 = 0; k4 < 16; k4++) {
        float4 wv = __ldg(&w4[k4]);
        #pragma unroll
        for (int r = 0; r < 32; r++) {
            float4 xv = *(const float4*)&Xs[r * 64 + k4 * 4];
            acc[r] += xv.x * wv.x + xv.y * wv.y + xv.z * wv.z + xv.w * wv.w;
        }
    }
    #pragma unroll
    for (int r = 0; r < 32; r++)
        Y[(size_t)(row0 + r) * HC + tid] = acc[r];
}

// ---------------- per-node GATv2 aggregation (online softmax) ----------------
// block = 128 threads = 4 warps; warp w = head w; lane owns channels {2*lane, 2*lane+1}
#define NODE_BLOCKS 2960
__global__ void __launch_bounds__(128)
k_node(const float* __restrict__ att, const float* __restrict__ bias,
       float* __restrict__ outp) {
    float* out = outp ? outp : g_h;
    int w = threadIdx.x >> 5;        // head
    int lane = threadIdx.x & 31;
    int hb = w * CC;                 // head base in the 256-wide row
    int co = hb + 2 * lane;          // this lane's channel offset (float2)

    float2 av = *(const float2*)&att[co];

    for (int n = blockIdx.x; n < NN; n += NODE_BLOCKS) {
        size_t nb = (size_t)n * HC + co;
        float2 xrv = *(const float2*)&g_xr[nb];

        // self-loop initializes the online-softmax state
        float2 xlv = *(const float2*)&g_xl[nb];
        float2 lev = *(const float2*)&g_le[nb];
        float m0 = xlv.x + xrv.x + lev.x; m0 = fmaxf(m0, NEG * m0);
        float m1 = xlv.y + xrv.y + lev.y; m1 = fmaxf(m1, NEG * m1);
        float t = m0 * av.x + m1 * av.y;
        #pragma unroll
        for (int o = 16; o; o >>= 1) t += __shfl_xor_sync(0xffffffffu, t, o);
        float mmax = t, denom = 1.f;
        float acc0 = xlv.x, acc1 = xlv.y;

        int beg = g_off[n], end = g_off[n + 1];
        #pragma unroll 2
        for (int i = beg; i < end; i++) {
            int2 er = __ldg(&g_csrE[i]);
            xlv = *(const float2*)&g_xl[(size_t)er.x * HC + co];
            float2 rpv = *(const float2*)&g_rp[(size_t)er.y * HC + co];
            m0 = xlv.x + xrv.x + rpv.x; m0 = fmaxf(m0, NEG * m0);
            m1 = xlv.y + xrv.y + rpv.y; m1 = fmaxf(m1, NEG * m1);
            t = m0 * av.x + m1 * av.y;
            #pragma unroll
            for (int o = 16; o; o >>= 1) t += __shfl_xor_sync(0xffffffffu, t, o);
            float nm = fmaxf(mmax, t);
            float sc = __expf(mmax - nm);
            float p  = __expf(t - nm);
            denom = denom * sc + p;
            acc0  = acc0 * sc + p * xlv.x;
            acc1  = acc1 * sc + p * xlv.y;
            mmax = nm;
        }

        __shared__ float sh[HH * CC];
        float inv = 1.f / denom;
        *(float2*)&sh[co] = make_float2(acc0 * inv, acc1 * inv);
        __syncthreads();
        int c = threadIdx.x;
        if (c < CC) {
            float v = 0.25f * (sh[c] + sh[CC + c] + sh[2 * CC + c] + sh[3 * CC + c]) + bias[c];
            out[(size_t)n * FD + c] = v;
        }
        __syncthreads();   // protect sh before next node iteration
    }
}

__global__ void k_copyrel(const float* __restrict__ rel, float* __restrict__ out) {
    int i = blockIdx.x * blockDim.x + threadIdx.x;
    if (i < RR * FD) out[i] = rel[i];
}

// ---------------- launch: kernel launches ONLY ----------------
extern "C" void kernel_launch(void* const* d_in, const int* in_sizes, int n_in,
                              void* d_out, int out_size) {
    const float* x    = (const float*)d_in[0];
    const int*   ei   = (const int*)d_in[1];     // int32 (JAX x64 disabled)
    const float* rel  = (const float*)d_in[2];
    const int*   ri   = (const int*)d_in[3];     // int32
    const float* Wt[2][3] = {{(const float*)d_in[4],  (const float*)d_in[6],  (const float*)d_in[8]},
                             {(const float*)d_in[11], (const float*)d_in[13], (const float*)d_in[15]}};
    const float* Bt[2][2] = {{(const float*)d_in[5],  (const float*)d_in[7]},
                             {(const float*)d_in[12], (const float*)d_in[14]}};
    const float* At[2]    = {(const float*)d_in[9],  (const float*)d_in[16]};
    const float* bt[2]    = {(const float*)d_in[10], (const float*)d_in[17]};
    float* out = (float*)d_out;

    const int* srcA = ei;
    const int* dstA = ei + EE;

    // ---- graph setup (shared across layers) ----
    k_zero_deg<<<(NN + 255) / 256, 256>>>();
    k_count<<<(EE + 255) / 256, 256>>>(dstA);
    k_scan<<<1, 1024>>>();
    k_csr<<<(EE + 255) / 256, 256>>>(srcA, dstA, ri);
    k_mean<<<NN, FD>>>(rel);

    // ---- two GATv2 layers ----
    for (int l = 0; l < 2; l++) {
        int xsel = l ? 1 : 0;                       // layer0: input x (arg), layer1: g_h
        float* ol = l ? out : nullptr;              // layer0 writes g_h
        k_gemm2<<<NN / 32, 256>>>(x, Wt[l][0], Bt[l][0], Wt[l][1], Bt[l][1], xsel); // -> g_xl, g_xr
        k_gemm1<<<NN / 32, 256>>>(x, 1, Wt[l][2], 0);   // g_mean -> g_le
        k_gemm1<<<RR / 32, 256>>>(rel, 0, Wt[l][2], 1); // rel    -> g_rp
        k_node<<<NODE_BLOCKS, 128>>>(At[l], bt[l], ol);
    }

    // trailing output: relations passthrough
    k_copyrel<<<(RR * FD + 255) / 256, 256>>>(rel, out + (size_t)NN * FD);
}

// round 8
// speedup vs baseline: 1.7137x; 1.0170x over previous
#include <cuda_runtime.h>

#define NN 20000      // nodes
#define EE 320000     // edges
#define FD 64         // features
#define HH 4          // heads
#define CC 64         // channels/head
#define HC 256        // HH*CC
#define RR 512        // relations
#define NEG 0.2f

// ---------------- scratch (device globals; no allocation anywhere) ----------------
__device__ float g_xl[NN * HC];
__device__ float g_xr[NN * HC];
__device__ float g_le[NN * HC];     // self-loop edge projection
__device__ float g_rp[RR * HC];     // relation projection table
__device__ float g_mean[NN * FD];   // per-node mean incoming edge_attr
__device__ float g_h[NN * FD];      // layer-0 output
__device__ int   g_deg[NN];
__device__ int   g_off[NN + 1];
__device__ int   g_cur[NN];
__device__ int2  g_csrE[EE];        // packed (src, ri) per CSR slot

// ---------------- setup kernels ----------------
__global__ void k_zero_deg() {
    int i = blockIdx.x * blockDim.x + threadIdx.x;
    if (i < NN) g_deg[i] = 0;
}

__global__ void k_count(const int* __restrict__ dst) {
    int e = blockIdx.x * blockDim.x + threadIdx.x;
    if (e < EE) atomicAdd(&g_deg[dst[e]], 1);
}

// single-block exclusive scan of g_deg -> g_off, also copies into g_cur
__global__ void k_scan() {
    __shared__ int carry;
    __shared__ int ws[32];
    int tid = threadIdx.x;
    int lane = tid & 31, wid = tid >> 5;
    if (tid == 0) carry = 0;
    __syncthreads();
    for (int base = 0; base < NN; base += 1024) {
        int idx = base + tid;
        int v = (idx < NN) ? g_deg[idx] : 0;
        int x = v;
        #pragma unroll
        for (int o = 1; o < 32; o <<= 1) {
            int y = __shfl_up_sync(0xffffffffu, x, o);
            if (lane >= o) x += y;
        }
        if (lane == 31) ws[wid] = x;
        __syncthreads();
        if (wid == 0) {
            int s = ws[lane];
            #pragma unroll
            for (int o = 1; o < 32; o <<= 1) {
                int y = __shfl_up_sync(0xffffffffu, s, o);
                if (lane >= o) s += y;
            }
            ws[lane] = s;
        }
        __syncthreads();
        int pre = carry + ((wid > 0) ? ws[wid - 1] : 0) + x - v;
        if (idx < NN) { g_off[idx] = pre; g_cur[idx] = pre; }
        __syncthreads();
        if (tid == 1023) carry = pre + v;
        __syncthreads();
    }
    if (threadIdx.x == 0) g_off[NN] = carry;
}

// scatter edges into CSR with packed (src, ri) payload
__global__ void k_csr(const int* __restrict__ src, const int* __restrict__ dst,
                      const int* __restrict__ ri) {
    int e = blockIdx.x * blockDim.x + threadIdx.x;
    if (e >= EE) return;
    int d = dst[e];
    int pos = atomicAdd(&g_cur[d], 1);
    g_csrE[pos] = make_int2(src[e], ri[e]);
}

// per-node mean of incoming relation rows, via CSR gather (no atomics)
__global__ void k_mean(const float* __restrict__ rel) {
    int n = blockIdx.x;
    int f = threadIdx.x;           // 64 threads
    int beg = g_off[n], end = g_off[n + 1];
    float s = 0.f;
    for (int i = beg; i < end; i++) {
        int r = g_csrE[i].y;
        s += __ldg(rel + r * FD + f);
    }
    int d = end - beg;
    g_mean[n * FD + f] = s * (1.0f / (float)(d > 0 ? d : 1));
}

// ---------------- GEMMs: Y[rows,256] = X[rows,64] @ W[256,64]^T (+bias) ----------------
// Row counts are exact multiples of 32 (20000, 512): no bounds checks.
__global__ void k_gemm2(const float* __restrict__ Xin,
                        const float* __restrict__ W0, const float* __restrict__ B0,
                        const float* __restrict__ W1, const float* __restrict__ B1,
                        int xsel) {
    const float* X = xsel ? g_h : Xin;
    __shared__ float Xs[32 * 64];
    int row0 = blockIdx.x * 32;
    int tid = threadIdx.x;  // 0..255, output column
    const float4* Xg = (const float4*)(X + (size_t)row0 * 64);
    float4* Xs4 = (float4*)Xs;
    Xs4[tid] = Xg[tid];
    Xs4[tid + 256] = Xg[tid + 256];
    __syncthreads();
    #pragma unroll 1
    for (int o = 0; o < 2; o++) {
        const float* W = o ? W1 : W0;
        const float* B = o ? B1 : B0;
        float* Y = o ? g_xr : g_xl;
        float acc[32];
        #pragma unroll
        for (int r = 0; r < 32; r++) acc[r] = 0.f;
        const float4* w4 = (const float4*)(W + tid * 64);
        #pragma unroll
        for (int k4 = 0; k4 < 16; k4++) {
            float4 wv = __ldg(&w4[k4]);
            #pragma unroll
            for (int r = 0; r < 32; r++) {
                float4 xv = *(const float4*)&Xs[r * 64 + k4 * 4];
                acc[r] += xv.x * wv.x + xv.y * wv.y + xv.z * wv.z + xv.w * wv.w;
            }
        }
        float bv = B[tid];
        #pragma unroll
        for (int r = 0; r < 32; r++)
            Y[(size_t)(row0 + r) * HC + tid] = acc[r] + bv;
    }
}

// single-output, bias-free GEMM: xsel 0 -> Xin arg, 1 -> g_mean; outsel 0 -> g_le, 1 -> g_rp
__global__ void k_gemm1(const float* __restrict__ Xin, int xsel,
                        const float* __restrict__ W, int outsel) {
    const float* X = xsel ? g_mean : Xin;
    float* Y = outsel ? g_rp : g_le;
    __shared__ float Xs[32 * 64];
    int row0 = blockIdx.x * 32;
    int tid = threadIdx.x;
    const float4* Xg = (const float4*)(X + (size_t)row0 * 64);
    float4* Xs4 = (float4*)Xs;
    Xs4[tid] = Xg[tid];
    Xs4[tid + 256] = Xg[tid + 256];
    __syncthreads();
    float acc[32];
    #pragma unroll
    for (int r = 0; r < 32; r++) acc[r] = 0.f;
    const float4* w4 = (const float4*)(W + tid * 64);
    #pragma unroll
    for (int k4 = 0; k4 < 16; k4++) {
        float4 wv = __ldg(&w4[k4]);
        #pragma unroll
        for (int r = 0; r < 32; r++) {
            float4 xv = *(const float4*)&Xs[r * 64 + k4 * 4];
            acc[r] += xv.x * wv.x + xv.y * wv.y + xv.z * wv.z + xv.w * wv.w;
        }
    }
    #pragma unroll
    for (int r = 0; r < 32; r++)
        Y[(size_t)(row0 + r) * HC + tid] = acc[r];
}

// ---------------- per-node GATv2 aggregation (grouped online softmax) ----------------
// block = 128 threads = 4 warps; warp = head.
// Warp splits into 4 groups of 8 lanes; each group runs an independent
// online-softmax chain over every 4th edge. ALL intra-group shuffles use the
// group-local 8-lane mask (groups have divergent trip counts; a full-mask
// shuffle there deadlocks). Final merge happens after reconvergence.
#define NODE_BLOCKS 2960
__global__ void __launch_bounds__(128)
k_node(const float* __restrict__ att, const float* __restrict__ bias,
       float* __restrict__ outp) {
    float* out = outp ? outp : g_h;
    int w = threadIdx.x >> 5;        // head
    int lane = threadIdx.x & 31;
    int g = lane >> 3;               // group 0..3
    int l8 = lane & 7;               // lane-in-group
    int co = w * CC + l8 * 8;        // this lane's 8-channel base (32B aligned)
    unsigned gm = 0xFFu << (g * 8);  // group-local shuffle mask

    float4 atA = *(const float4*)&att[co];
    float4 atB = *(const float4*)&att[co + 4];

    __shared__ float sh[HH * CC];

    for (int n = blockIdx.x; n < NN; n += NODE_BLOCKS) {
        size_t nb = (size_t)n * HC + co;
        float4 xrA = *(const float4*)&g_xr[nb];
        float4 xrB = *(const float4*)&g_xr[nb + 4];

        float mmax = -1e30f, denom = 0.f;
        float ac[8];
        #pragma unroll
        for (int j = 0; j < 8; j++) ac[j] = 0.f;

        // group 0 seeds with the self-loop (group-mask shuffles only)
        if (g == 0) {
            float4 xlA = *(const float4*)&g_xl[nb];
            float4 xlB = *(const float4*)&g_xl[nb + 4];
            float4 leA = *(const float4*)&g_le[nb];
            float4 leB = *(const float4*)&g_le[nb + 4];
            float v[8] = {xlA.x + xrA.x + leA.x, xlA.y + xrA.y + leA.y,
                          xlA.z + xrA.z + leA.z, xlA.w + xrA.w + leA.w,
                          xlB.x + xrB.x + leB.x, xlB.y + xrB.y + leB.y,
                          xlB.z + xrB.z + leB.z, xlB.w + xrB.w + leB.w};
            float a[8] = {atA.x, atA.y, atA.z, atA.w, atB.x, atB.y, atB.z, atB.w};
            float tp = 0.f;
            #pragma unroll
            for (int j = 0; j < 8; j++) { float m = fmaxf(v[j], NEG * v[j]); tp += m * a[j]; }
            #pragma unroll
            for (int o = 1; o < 8; o <<= 1) tp += __shfl_xor_sync(gm, tp, o);
            mmax = tp; denom = 1.f;
            ac[0] = xlA.x; ac[1] = xlA.y; ac[2] = xlA.z; ac[3] = xlA.w;
            ac[4] = xlB.x; ac[5] = xlB.y; ac[6] = xlB.z; ac[7] = xlB.w;
        }

        int beg = g_off[n], end = g_off[n + 1];
        #pragma unroll 2
        for (int i = beg + g; i < end; i += 4) {
            int2 er = __ldg(&g_csrE[i]);
            size_t sb = (size_t)er.x * HC + co;
            size_t rb = (size_t)er.y * HC + co;
            float4 xlA = *(const float4*)&g_xl[sb];
            float4 xlB = *(const float4*)&g_xl[sb + 4];
            float4 rpA = *(const float4*)&g_rp[rb];
            float4 rpB = *(const float4*)&g_rp[rb + 4];
            float xv[8] = {xlA.x, xlA.y, xlA.z, xlA.w, xlB.x, xlB.y, xlB.z, xlB.w};
            float v[8] = {xlA.x + xrA.x + rpA.x, xlA.y + xrA.y + rpA.y,
                          xlA.z + xrA.z + rpA.z, xlA.w + xrA.w + rpA.w,
                          xlB.x + xrB.x + rpB.x, xlB.y + xrB.y + rpB.y,
                          xlB.z + xrB.z + rpB.z, xlB.w + xrB.w + rpB.w};
            float a[8] = {atA.x, atA.y, atA.z, atA.w, atB.x, atB.y, atB.z, atB.w};
            float tp = 0.f;
            #pragma unroll
            for (int j = 0; j < 8; j++) { float m = fmaxf(v[j], NEG * v[j]); tp += m * a[j]; }
            #pragma unroll
            for (int o = 1; o < 8; o <<= 1) tp += __shfl_xor_sync(gm, tp, o);
            float nm = fmaxf(mmax, tp);
            float sc = __expf(mmax - nm);
            float p  = __expf(tp - nm);
            denom = denom * sc + p;
            #pragma unroll
            for (int j = 0; j < 8; j++) ac[j] = ac[j] * sc + p * xv[j];
            mmax = nm;
        }

        // merge the 4 group states (lanes reconverged; full-mask OK)
        #pragma unroll
        for (int off = 8; off <= 16; off <<= 1) {
            float om = __shfl_xor_sync(0xffffffffu, mmax, off);
            float od = __shfl_xor_sync(0xffffffffu, denom, off);
            float oa[8];
            #pragma unroll
            for (int j = 0; j < 8; j++) oa[j] = __shfl_xor_sync(0xffffffffu, ac[j], off);
            float nm = fmaxf(mmax, om);
            float s1 = __expf(mmax - nm);
            float s2 = __expf(om - nm);
            denom = denom * s1 + od * s2;
            #pragma unroll
            for (int j = 0; j < 8; j++) ac[j] = ac[j] * s1 + oa[j] * s2;
            mmax = nm;
        }

        if (g == 0) {
            float inv = 1.f / denom;
            *(float4*)&sh[co]     = make_float4(ac[0] * inv, ac[1] * inv, ac[2] * inv, ac[3] * inv);
            *(float4*)&sh[co + 4] = make_float4(ac[4] * inv, ac[5] * inv, ac[6] * inv, ac[7] * inv);
        }
        __syncthreads();
        int c = threadIdx.x;
        if (c < CC) {
            float v = 0.25f * (sh[c] + sh[CC + c] + sh[2 * CC + c] + sh[3 * CC + c]) + bias[c];
            out[(size_t)n * FD + c] = v;
        }
        __syncthreads();   // protect sh before next node iteration
    }
}

__global__ void k_copyrel(const float* __restrict__ rel, float* __restrict__ out) {
    int i = blockIdx.x * blockDim.x + threadIdx.x;
    if (i < RR * FD) out[i] = rel[i];
}

// ---------------- launch: kernel launches ONLY ----------------
extern "C" void kernel_launch(void* const* d_in, const int* in_sizes, int n_in,
                              void* d_out, int out_size) {
    const float* x    = (const float*)d_in[0];
    const int*   ei   = (const int*)d_in[1];     // int32 (JAX x64 disabled)
    const float* rel  = (const float*)d_in[2];
    const int*   ri   = (const int*)d_in[3];     // int32
    const float* Wt[2][3] = {{(const float*)d_in[4],  (const float*)d_in[6],  (const float*)d_in[8]},
                             {(const float*)d_in[11], (const float*)d_in[13], (const float*)d_in[15]}};
    const float* Bt[2][2] = {{(const float*)d_in[5],  (const float*)d_in[7]},
                             {(const float*)d_in[12], (const float*)d_in[14]}};
    const float* At[2]    = {(const float*)d_in[9],  (const float*)d_in[16]};
    const float* bt[2]    = {(const float*)d_in[10], (const float*)d_in[17]};
    float* out = (float*)d_out;

    const int* srcA = ei;
    const int* dstA = ei + EE;

    // ---- graph setup (shared across layers) ----
    k_zero_deg<<<(NN + 255) / 256, 256>>>();
    k_count<<<(EE + 255) / 256, 256>>>(dstA);
    k_scan<<<1, 1024>>>();
    k_csr<<<(EE + 255) / 256, 256>>>(srcA, dstA, ri);
    k_mean<<<NN, FD>>>(rel);

    // ---- two GATv2 layers ----
    for (int l = 0; l < 2; l++) {
        int xsel = l ? 1 : 0;                       // layer0: input x (arg), layer1: g_h
        float* ol = l ? out : nullptr;              // layer0 writes g_h
        k_gemm2<<<NN / 32, 256>>>(x, Wt[l][0], Bt[l][0], Wt[l][1], Bt[l][1], xsel); // -> g_xl, g_xr
        k_gemm1<<<NN / 32, 256>>>(x, 1, Wt[l][2], 0);   // g_mean -> g_le
        k_gemm1<<<RR / 32, 256>>>(rel, 0, Wt[l][2], 1); // rel    -> g_rp
        k_node<<<NODE_BLOCKS, 128>>>(At[l], bt[l], ol);
    }

    // trailing output: relations passthrough
    k_copyrel<<<(RR * FD + 255) / 256, 256>>>(rel, out + (size_t)NN * FD);
}